// round 12
// baseline (speedup 1.0000x reference)
#include <cuda_runtime.h>
#include <cuda_bf16.h>
#include <cstdint>

#define NN     4096
#define WORDS  64
#define HID    256
#define VOCAB  50257
#define NCLASS 4
#define NLEAF  2048

#define NCLUST 8                  // node slots = clusters (64 CTAs total -> fits one die)
#define CSIZE  8                  // CTAs per cluster (one 32-row chunk each)
#define GSCAN  (NCLUST * CSIZE)   // 64 persistent CTAs

// ---------------- scratch (device globals; no mallocs allowed) ----------------
__device__ float d_ET[(size_t)VOCAB * HID];   // E transposed: [VOCAB][HID]
__device__ float d_X [(size_t)NN * HID];
__device__ float d_Yz[(size_t)NN * HID];
__device__ float d_Yr[(size_t)NN * HID];
__device__ float d_Yh[(size_t)NN * HID];
__device__ float d_H [(size_t)NN * HID];
__device__ int   d_par[NN];
__device__ int   d_order[NN];
__device__ int   d_level_start[NN + 1];
__device__ int   d_offs[NN];
__device__ int   d_nlevels;
__device__ int   d_cnt_h[NN];   // per-node: # of chunk-CTAs that published h
__device__ float d_Pmax[16 * HID];

// ---------------- E transpose: E(HID,VOCAB) -> ET(VOCAB,HID) ----------------
__global__ void transposeE(const float* __restrict__ E) {
    __shared__ float tile[32][33];
    int v0 = blockIdx.x * 32, h0 = blockIdx.y * 32;
    int x = threadIdx.x, y = threadIdx.y;   // 32 x 8
    #pragma unroll
    for (int i = 0; i < 32; i += 8) {
        int h = h0 + y + i, v = v0 + x;
        tile[y + i][x] = (v < VOCAB) ? E[(size_t)h * VOCAB + v] : 0.f;
    }
    __syncthreads();
    #pragma unroll
    for (int i = 0; i < 32; i += 8) {
        int v = v0 + y + i;
        if (v < VOCAB) d_ET[(size_t)v * HID + h0 + x] = tile[x][y + i];
    }
}

// ---------------- X[n,h] = sum_w ET[tree[n,w], h];  also H[0] = X[0] ----------------
__global__ void gatherX(const int* __restrict__ tree) {
    __shared__ int wv[WORDS];
    int n = blockIdx.x;
    if (threadIdx.x < WORDS) wv[threadIdx.x] = tree[n * WORDS + threadIdx.x];
    __syncthreads();
    int h = threadIdx.x;
    float acc = 0.f;
    #pragma unroll 8
    for (int w = 0; w < WORDS; w++) acc += d_ET[(size_t)wv[w] * HID + h];
    d_X[(size_t)n * HID + h] = acc;
    if (n == 0) d_H[h] = acc;   // node_h0[0] = X[0]
}

// ---------------- Y{z,r,h} = X @ W{z,r,h}^T  (4096x256 @ 256x256) ----------------
__global__ void gemm3(const float* __restrict__ Wz, const float* __restrict__ Wr,
                      const float* __restrict__ Wh) {
    const float* W = (blockIdx.z == 0) ? Wz : (blockIdx.z == 1) ? Wr : Wh;
    float* Y       = (blockIdx.z == 0) ? d_Yz : (blockIdx.z == 1) ? d_Yr : d_Yh;
    __shared__ float As[128][17];
    __shared__ float Bs[64][17];
    const int tid = threadIdx.x;
    const int tx = tid & 15, ty = tid >> 4;
    const int bm = blockIdx.x, bn = blockIdx.y;
    float acc[8][4];
    #pragma unroll
    for (int i = 0; i < 8; i++)
        #pragma unroll
        for (int j = 0; j < 4; j++) acc[i][j] = 0.f;

    const int arow = tid >> 1, ac8 = (tid & 1) * 8;
    const int brow = tid >> 2, bc4 = (tid & 3) * 4;

    for (int k0 = 0; k0 < HID; k0 += 16) {
        float4 va = *(const float4*)(d_X + (size_t)(bm * 128 + arow) * HID + k0 + ac8);
        float4 vb = *(const float4*)(d_X + (size_t)(bm * 128 + arow) * HID + k0 + ac8 + 4);
        As[arow][ac8 + 0] = va.x; As[arow][ac8 + 1] = va.y;
        As[arow][ac8 + 2] = va.z; As[arow][ac8 + 3] = va.w;
        As[arow][ac8 + 4] = vb.x; As[arow][ac8 + 5] = vb.y;
        As[arow][ac8 + 6] = vb.z; As[arow][ac8 + 7] = vb.w;
        float4 wb = *(const float4*)(W + (size_t)(bn * 64 + brow) * HID + k0 + bc4);
        Bs[brow][bc4 + 0] = wb.x; Bs[brow][bc4 + 1] = wb.y;
        Bs[brow][bc4 + 2] = wb.z; Bs[brow][bc4 + 3] = wb.w;
        __syncthreads();
        #pragma unroll
        for (int kk = 0; kk < 16; kk++) {
            float a[8], b[4];
            #pragma unroll
            for (int i = 0; i < 8; i++) a[i] = As[ty * 8 + i][kk];
            #pragma unroll
            for (int j = 0; j < 4; j++) b[j] = Bs[tx * 4 + j][kk];
            #pragma unroll
            for (int i = 0; i < 8; i++)
                #pragma unroll
                for (int j = 0; j < 4; j++) acc[i][j] = fmaf(a[i], b[j], acc[i][j]);
        }
        __syncthreads();
    }
    #pragma unroll
    for (int i = 0; i < 8; i++) {
        int m = bm * 128 + ty * 8 + i;
        float4 o = make_float4(acc[i][0], acc[i][1], acc[i][2], acc[i][3]);
        *(float4*)(Y + (size_t)m * HID + bn * 64 + tx * 4) = o;
    }
}

// ---------------- prep: levels (pointer doubling) + counting sort + counter reset ----------------
__global__ void prep(const int* __restrict__ edge) {
    __shared__ int s_jump[NN];
    __shared__ int s_add[NN];
    __shared__ int s_scan[1024];
    __shared__ int s_maxl;
    const int tid = threadIdx.x;
    if (tid == 0) s_maxl = 0;
    for (int i = tid; i < NN; i += 1024) {
        int p = edge[2 * i];
        d_par[i]  = p;
        s_jump[i] = (i == 0) ? 0 : p;
        s_add[i]  = (i == 0) ? 0 : 1;
        d_cnt_h[i] = (i == 0) ? CSIZE : 0;   // node 0's h comes from gatherX
    }
    __syncthreads();
    for (int r = 0; r < 12; r++) {
        int nj[4], na[4];
        #pragma unroll
        for (int k = 0; k < 4; k++) {
            int i = tid + k * 1024;
            int j = s_jump[i];
            nj[k] = s_jump[j];
            na[k] = s_add[i] + s_add[j];
        }
        __syncthreads();
        #pragma unroll
        for (int k = 0; k < 4; k++) {
            int i = tid + k * 1024;
            s_jump[i] = nj[k];
            s_add[i]  = na[k];
        }
        __syncthreads();
    }
    // s_add[i] == level(i). Histogram into s_jump (reused).
    for (int i = tid; i < NN; i += 1024) s_jump[i] = 0;
    __syncthreads();
    #pragma unroll
    for (int k = 0; k < 4; k++) {
        int i = tid + k * 1024;
        atomicMax(&s_maxl, s_add[i]);
        atomicAdd(&s_jump[s_add[i]], 1);
    }
    __syncthreads();
    int c0 = s_jump[4 * tid], c1 = s_jump[4 * tid + 1];
    int c2 = s_jump[4 * tid + 2], c3 = s_jump[4 * tid + 3];
    int part = c0 + c1 + c2 + c3;
    s_scan[tid] = part;
    __syncthreads();
    for (int off = 1; off < 1024; off <<= 1) {
        int v = (tid >= off) ? s_scan[tid - off] : 0;
        __syncthreads();
        s_scan[tid] += v;
        __syncthreads();
    }
    int basep = s_scan[tid] - part;
    d_level_start[4 * tid]     = basep;
    d_level_start[4 * tid + 1] = basep + c0;
    d_level_start[4 * tid + 2] = basep + c0 + c1;
    d_level_start[4 * tid + 3] = basep + c0 + c1 + c2;
    d_offs[4 * tid]     = basep;
    d_offs[4 * tid + 1] = basep + c0;
    d_offs[4 * tid + 2] = basep + c0 + c1;
    d_offs[4 * tid + 3] = basep + c0 + c1 + c2;
    if (tid == 0) d_level_start[NN] = NN;
    __syncthreads();
    #pragma unroll
    for (int k = 0; k < 4; k++) {
        int i = tid + k * 1024;
        int lvl = s_add[i];
        int pos = atomicAdd(&d_offs[lvl], 1);
        d_order[pos] = i;
    }
    if (tid == 0) d_nlevels = s_maxl + 1;
}

// ---------------- persistent clustered dataflow GRU scan ----------------
__device__ __forceinline__ float sigm(float x) { return 1.f / (1.f + __expf(-x)); }

__device__ __forceinline__ unsigned int smem_u32(const void* p) {
    return (unsigned int)__cvta_generic_to_shared(p);
}
__device__ __forceinline__ void dsmem_st(unsigned int local_addr, unsigned int peer, float v) {
    unsigned int rem;
    asm volatile("mapa.shared::cluster.u32 %0, %1, %2;" : "=r"(rem) : "r"(local_addr), "r"(peer));
    asm volatile("st.shared::cluster.f32 [%0], %1;" :: "r"(rem), "f"(v) : "memory");
}
#define CLUSTER_SYNC() do { \
    asm volatile("barrier.cluster.arrive.aligned;" ::: "memory"); \
    asm volatile("barrier.cluster.wait.aligned;"   ::: "memory"); \
} while (0)

__global__ void __launch_bounds__(256, 1)
scan_kernel(const float* __restrict__ Uz, const float* __restrict__ Ur,
            const float* __restrict__ Uh, const float* __restrict__ bz,
            const float* __restrict__ br, const float* __restrict__ bh) {
    __shared__ float s_ph[HID];   // parent h (full vector)
    __shared__ float s_u [HID];   // ph * r   (full vector)
    const int tid   = threadIdx.x;
    const int sub   = tid & 7;                  // 8 lanes per row
    const int rrel  = tid >> 3;                 // 0..31 row within chunk
    const unsigned int rank = blockIdx.x & 7;   // cluster rank == row chunk
    const int clid  = blockIdx.x >> 3;          // cluster id == node slot
    const int r0    = (int)rank * 32 + rrel;    // my output row

    // loop-invariant U slices in registers
    float4 uzr[8], urr[8], uhr[8];
    {
        const float* a = Uz + (size_t)r0 * HID + sub * 4;
        const float* b = Ur + (size_t)r0 * HID + sub * 4;
        const float* c = Uh + (size_t)r0 * HID + sub * 4;
        #pragma unroll
        for (int k = 0; k < 8; k++) {
            uzr[k] = *(const float4*)(a + k * 32);
            urr[k] = *(const float4*)(b + k * 32);
            uhr[k] = *(const float4*)(c + k * 32);
        }
    }
    const float bzv = bz[r0], brv = br[r0], bhv = bh[r0];
    const unsigned int a_u  = smem_u32(&s_u [r0]);
    const unsigned int a_ph = smem_u32(&s_ph[r0]);
    const int nlev = d_nlevels;
    int last = -1;   // node whose h currently lives in s_ph

    for (int L = 1; L < nlev; L++) {
        const int s = d_level_start[L];
        const int e = d_level_start[L + 1];
        const int W = e - s;

        for (int i = clid; i < W; i += NCLUST) {
            const int n = d_order[s + i];
            const int p = d_par[n];

            // prefetch pre-GEMM activations (independent of parent readiness)
            float yz = 0.f, yr = 0.f, yh = 0.f;
            if (sub == 0) {
                yz = d_Yz[(size_t)n * HID + r0];
                yr = d_Yr[(size_t)n * HID + r0];
                yh = d_Yh[(size_t)n * HID + r0];
            }

            if (p != last) {           // slow path: parent produced by another cluster
                if (tid == 0) {
                    volatile int* c = &d_cnt_h[p];
                    while (*c < CSIZE) { __nanosleep(20); }
                    __threadfence();   // acquire
                }
                __syncthreads();
                s_ph[tid] = d_H[(size_t)p * HID + tid];
                __syncthreads();
            }

            // ---- phase 1: z, r rows; u = ph (.) r ----
            float az = 0.f, ar = 0.f;
            #pragma unroll
            for (int k = 0; k < 8; k++) {
                const float4 pv = *(const float4*)(&s_ph[sub * 4 + k * 32]);
                az = fmaf(uzr[k].x, pv.x, fmaf(uzr[k].y, pv.y, fmaf(uzr[k].z, pv.z, fmaf(uzr[k].w, pv.w, az))));
                ar = fmaf(urr[k].x, pv.x, fmaf(urr[k].y, pv.y, fmaf(urr[k].z, pv.z, fmaf(urr[k].w, pv.w, ar))));
            }
            #pragma unroll
            for (int o = 1; o < 8; o <<= 1) {
                az += __shfl_xor_sync(0xffffffffu, az, o);
                ar += __shfl_xor_sync(0xffffffffu, ar, o);
            }
            float zv = 0.f, phv = 0.f;
            if (sub == 0) {
                phv = s_ph[r0];
                zv  = sigm(yz + az + bzv);
                float rr = sigm(yr + ar + brv);
                float uval = phv * rr;
                #pragma unroll
                for (unsigned int k = 0; k < CSIZE; k++) dsmem_st(a_u, k, uval);
            }
            CLUSTER_SYNC();   // u fully assembled in every CTA's s_u

            // ---- phase 2: c = tanh(yh + Uh@u); h = z*ph + (1-z)*c ----
            float ah = 0.f;
            #pragma unroll
            for (int k = 0; k < 8; k++) {
                const float4 pv = *(const float4*)(&s_u[sub * 4 + k * 32]);
                ah = fmaf(uhr[k].x, pv.x, fmaf(uhr[k].y, pv.y, fmaf(uhr[k].z, pv.z, fmaf(uhr[k].w, pv.w, ah))));
            }
            #pragma unroll
            for (int o = 1; o < 8; o <<= 1)
                ah += __shfl_xor_sync(0xffffffffu, ah, o);

            if (sub == 0) {
                float c = tanhf(yh + ah + bhv);
                float hnew = zv * phv + (1.f - zv) * c;
                #pragma unroll
                for (unsigned int k = 0; k < CSIZE; k++) dsmem_st(a_ph, k, hnew);  // chain fast path
                d_H[(size_t)n * HID + r0] = hnew;                                  // global publish
            }
            CLUSTER_SYNC();   // h visible in every CTA's s_ph

            // cross-cluster signal (off the chain critical path)
            if (tid == 0) {
                __threadfence();
                atomicAdd(&d_cnt_h[n], 1);
            }
            last = n;
        }
    }
}

// ---------------- leaf max (partial) ----------------
__global__ void leafmax(const int* __restrict__ leaf) {
    int b = blockIdx.x, tid = threadIdx.x;
    float m = -1e30f;
    for (int l = b * 128; l < (b + 1) * 128; l++) {
        int idx = leaf[l];
        m = fmaxf(m, d_H[(size_t)idx * HID + tid]);
    }
    d_Pmax[b * HID + tid] = m;
}

// ---------------- combine + W_out matvec + softmax + loss ----------------
__global__ void finalk(const float* __restrict__ y, const float* __restrict__ Wout,
                       const float* __restrict__ bout, float* __restrict__ out,
                       int out_size) {
    __shared__ float fs[HID];
    __shared__ float logits[NCLASS];
    int tid = threadIdx.x;
    float m = -1e30f;
    #pragma unroll
    for (int b = 0; b < 16; b++) m = fmaxf(m, d_Pmax[b * HID + tid]);
    fs[tid] = m;
    __syncthreads();
    if (tid < NCLASS) {
        float acc = 0.f;
        for (int h = 0; h < HID; h++) acc = fmaf(Wout[tid * HID + h], fs[h], acc);
        logits[tid] = acc + bout[tid];
    }
    __syncthreads();
    if (tid == 0) {
        float mx = logits[0];
        for (int c = 1; c < NCLASS; c++) mx = fmaxf(mx, logits[c]);
        float ex[NCLASS], ssum = 0.f;
        for (int c = 0; c < NCLASS; c++) { ex[c] = __expf(logits[c] - mx); ssum += ex[c]; }
        float loss = 0.f;
        for (int c = 0; c < NCLASS; c++) {
            float p = ex[c] / ssum;
            if (c < out_size) out[c] = p;
            float d = y[c] - p;
            loss += d * d;
        }
        if (out_size > NCLASS) out[NCLASS] = loss;
    }
}

// ---------------- launcher ----------------
extern "C" void kernel_launch(void* const* d_in, const int* in_sizes, int n_in,
                              void* d_out, int out_size) {
    const int*   tree = (const int*)d_in[0];
    const int*   edge = (const int*)d_in[1];
    const int*   leaf = (const int*)d_in[2];
    const float* y    = (const float*)d_in[3];
    const float* E    = (const float*)d_in[4];
    const float* Wz   = (const float*)d_in[5];
    const float* Uz   = (const float*)d_in[6];
    const float* bz   = (const float*)d_in[7];
    const float* Wr   = (const float*)d_in[8];
    const float* Ur   = (const float*)d_in[9];
    const float* br   = (const float*)d_in[10];
    const float* Wh   = (const float*)d_in[11];
    const float* Uh   = (const float*)d_in[12];
    const float* bh   = (const float*)d_in[13];
    const float* Wout = (const float*)d_in[14];
    const float* bout = (const float*)d_in[15];
    float* out = (float*)d_out;

    transposeE<<<dim3((VOCAB + 31) / 32, HID / 32), dim3(32, 8)>>>(E);
    gatherX<<<NN, HID>>>(tree);
    gemm3<<<dim3(NN / 128, HID / 64, 3), 256>>>(Wz, Wr, Wh);
    prep<<<1, 1024>>>(edge);

    // clustered scan launch (8 clusters x 8 CTAs = 64 CTAs; fits a single die)
    {
        cudaLaunchConfig_t cfg = {};
        cfg.gridDim  = dim3(GSCAN, 1, 1);
        cfg.blockDim = dim3(256, 1, 1);
        cfg.dynamicSmemBytes = 0;
        cfg.stream = 0;
        cudaLaunchAttribute attr[1];
        attr[0].id = cudaLaunchAttributeClusterDimension;
        attr[0].val.clusterDim.x = CSIZE;
        attr[0].val.clusterDim.y = 1;
        attr[0].val.clusterDim.z = 1;
        cfg.attrs = attr;
        cfg.numAttrs = 1;
        cudaLaunchKernelEx(&cfg, scan_kernel, Uz, Ur, Uh, bz, br, bh);
    }

    leafmax<<<16, HID>>>(leaf);
    finalk<<<1, HID>>>(y, Wout, bout, out, out_size);
}

// round 15
// speedup vs baseline: 1.9241x; 1.9241x over previous
#include <cuda_runtime.h>
#include <cuda_bf16.h>
#include <cstdint>

#define NN     4096
#define WORDS  64
#define HID    256
#define VOCAB  50257
#define NCLASS 4
#define NLEAF  2048

#define NSLOT  16            // node slots
#define GSCAN  (NSLOT * 8)   // 128 persistent CTAs: 8 row-chunks x 16 node slots

// ---------------- scratch (device globals; no mallocs allowed) ----------------
__device__ float d_ET[(size_t)VOCAB * HID];   // E transposed: [VOCAB][HID]
__device__ float d_X [(size_t)NN * HID];
__device__ float d_Yz[(size_t)NN * HID];
__device__ float d_Yr[(size_t)NN * HID];
__device__ float d_Yh[(size_t)NN * HID];
__device__ float d_H [(size_t)NN * HID];
__device__ float d_Ubuf[(size_t)NN * HID];
__device__ int   d_par[NN];
__device__ int   d_order[NN];
__device__ int   d_level_start[NN + 1];
__device__ int   d_offs[NN];
__device__ int   d_nlevels;
__device__ int   d_cnt_u[NN];   // per-node: # chunk-CTAs done with phase 1 (u rows)
__device__ int   d_cnt_h[NN];   // per-node: # chunk-CTAs done with phase 2 (h rows)
__device__ float d_Pmax[16 * HID];

// ---------------- E transpose: E(HID,VOCAB) -> ET(VOCAB,HID) ----------------
__global__ void transposeE(const float* __restrict__ E) {
    __shared__ float tile[32][33];
    int v0 = blockIdx.x * 32, h0 = blockIdx.y * 32;
    int x = threadIdx.x, y = threadIdx.y;   // 32 x 8
    #pragma unroll
    for (int i = 0; i < 32; i += 8) {
        int h = h0 + y + i, v = v0 + x;
        tile[y + i][x] = (v < VOCAB) ? E[(size_t)h * VOCAB + v] : 0.f;
    }
    __syncthreads();
    #pragma unroll
    for (int i = 0; i < 32; i += 8) {
        int v = v0 + y + i;
        if (v < VOCAB) d_ET[(size_t)v * HID + h0 + x] = tile[x][y + i];
    }
}

// ---------------- X[n,h] = sum_w ET[tree[n,w], h];  also H[0] = X[0] ----------------
__global__ void gatherX(const int* __restrict__ tree) {
    __shared__ int wv[WORDS];
    int n = blockIdx.x;
    if (threadIdx.x < WORDS) wv[threadIdx.x] = tree[n * WORDS + threadIdx.x];
    __syncthreads();
    int h = threadIdx.x;
    float acc = 0.f;
    #pragma unroll 8
    for (int w = 0; w < WORDS; w++) acc += d_ET[(size_t)wv[w] * HID + h];
    d_X[(size_t)n * HID + h] = acc;
    if (n == 0) d_H[h] = acc;   // node_h0[0] = X[0]
}

// ---------------- Y{z,r,h} = X @ W{z,r,h}^T  (4096x256 @ 256x256) ----------------
__global__ void gemm3(const float* __restrict__ Wz, const float* __restrict__ Wr,
                      const float* __restrict__ Wh) {
    const float* W = (blockIdx.z == 0) ? Wz : (blockIdx.z == 1) ? Wr : Wh;
    float* Y       = (blockIdx.z == 0) ? d_Yz : (blockIdx.z == 1) ? d_Yr : d_Yh;
    __shared__ float As[128][17];
    __shared__ float Bs[64][17];
    const int tid = threadIdx.x;
    const int tx = tid & 15, ty = tid >> 4;
    const int bm = blockIdx.x, bn = blockIdx.y;
    float acc[8][4];
    #pragma unroll
    for (int i = 0; i < 8; i++)
        #pragma unroll
        for (int j = 0; j < 4; j++) acc[i][j] = 0.f;

    const int arow = tid >> 1, ac8 = (tid & 1) * 8;
    const int brow = tid >> 2, bc4 = (tid & 3) * 4;

    for (int k0 = 0; k0 < HID; k0 += 16) {
        float4 va = *(const float4*)(d_X + (size_t)(bm * 128 + arow) * HID + k0 + ac8);
        float4 vb = *(const float4*)(d_X + (size_t)(bm * 128 + arow) * HID + k0 + ac8 + 4);
        As[arow][ac8 + 0] = va.x; As[arow][ac8 + 1] = va.y;
        As[arow][ac8 + 2] = va.z; As[arow][ac8 + 3] = va.w;
        As[arow][ac8 + 4] = vb.x; As[arow][ac8 + 5] = vb.y;
        As[arow][ac8 + 6] = vb.z; As[arow][ac8 + 7] = vb.w;
        float4 wb = *(const float4*)(W + (size_t)(bn * 64 + brow) * HID + k0 + bc4);
        Bs[brow][bc4 + 0] = wb.x; Bs[brow][bc4 + 1] = wb.y;
        Bs[brow][bc4 + 2] = wb.z; Bs[brow][bc4 + 3] = wb.w;
        __syncthreads();
        #pragma unroll
        for (int kk = 0; kk < 16; kk++) {
            float a[8], b[4];
            #pragma unroll
            for (int i = 0; i < 8; i++) a[i] = As[ty * 8 + i][kk];
            #pragma unroll
            for (int j = 0; j < 4; j++) b[j] = Bs[tx * 4 + j][kk];
            #pragma unroll
            for (int i = 0; i < 8; i++)
                #pragma unroll
                for (int j = 0; j < 4; j++) acc[i][j] = fmaf(a[i], b[j], acc[i][j]);
        }
        __syncthreads();
    }
    #pragma unroll
    for (int i = 0; i < 8; i++) {
        int m = bm * 128 + ty * 8 + i;
        float4 o = make_float4(acc[i][0], acc[i][1], acc[i][2], acc[i][3]);
        *(float4*)(Y + (size_t)m * HID + bn * 64 + tx * 4) = o;
    }
}

// ---------------- prep: levels (pointer doubling) + counting sort + counter reset ----------------
__global__ void prep(const int* __restrict__ edge) {
    __shared__ int s_jump[NN];
    __shared__ int s_add[NN];
    __shared__ int s_scan[1024];
    __shared__ int s_maxl;
    const int tid = threadIdx.x;
    if (tid == 0) s_maxl = 0;
    for (int i = tid; i < NN; i += 1024) {
        int p = edge[2 * i];
        d_par[i]  = p;
        s_jump[i] = (i == 0) ? 0 : p;
        s_add[i]  = (i == 0) ? 0 : 1;
        d_cnt_u[i] = 0;
        d_cnt_h[i] = (i == 0) ? 8 : 0;   // node 0's h comes from gatherX
    }
    __syncthreads();
    for (int r = 0; r < 12; r++) {
        int nj[4], na[4];
        #pragma unroll
        for (int k = 0; k < 4; k++) {
            int i = tid + k * 1024;
            int j = s_jump[i];
            nj[k] = s_jump[j];
            na[k] = s_add[i] + s_add[j];
        }
        __syncthreads();
        #pragma unroll
        for (int k = 0; k < 4; k++) {
            int i = tid + k * 1024;
            s_jump[i] = nj[k];
            s_add[i]  = na[k];
        }
        __syncthreads();
    }
    // s_add[i] == level(i). Histogram into s_jump (reused).
    for (int i = tid; i < NN; i += 1024) s_jump[i] = 0;
    __syncthreads();
    #pragma unroll
    for (int k = 0; k < 4; k++) {
        int i = tid + k * 1024;
        atomicMax(&s_maxl, s_add[i]);
        atomicAdd(&s_jump[s_add[i]], 1);
    }
    __syncthreads();
    int c0 = s_jump[4 * tid], c1 = s_jump[4 * tid + 1];
    int c2 = s_jump[4 * tid + 2], c3 = s_jump[4 * tid + 3];
    int part = c0 + c1 + c2 + c3;
    s_scan[tid] = part;
    __syncthreads();
    for (int off = 1; off < 1024; off <<= 1) {
        int v = (tid >= off) ? s_scan[tid - off] : 0;
        __syncthreads();
        s_scan[tid] += v;
        __syncthreads();
    }
    int basep = s_scan[tid] - part;
    d_level_start[4 * tid]     = basep;
    d_level_start[4 * tid + 1] = basep + c0;
    d_level_start[4 * tid + 2] = basep + c0 + c1;
    d_level_start[4 * tid + 3] = basep + c0 + c1 + c2;
    d_offs[4 * tid]     = basep;
    d_offs[4 * tid + 1] = basep + c0;
    d_offs[4 * tid + 2] = basep + c0 + c1;
    d_offs[4 * tid + 3] = basep + c0 + c1 + c2;
    if (tid == 0) d_level_start[NN] = NN;
    __syncthreads();
    #pragma unroll
    for (int k = 0; k < 4; k++) {
        int i = tid + k * 1024;
        int lvl = s_add[i];
        int pos = atomicAdd(&d_offs[lvl], 1);
        d_order[pos] = i;
    }
    if (tid == 0) d_nlevels = s_maxl + 1;
}

// ---------------- persistent dataflow GRU scan (lean handshakes) ----------------
__device__ __forceinline__ float sigm(float x) { return 1.f / (1.f + __expf(-x)); }

// All threads poll with acquire loads; fast path sleep-free, backoff after 64 tries.
__device__ __forceinline__ void wait_ge8(int* c) {
    int v, tries = 0;
    for (;;) {
        asm volatile("ld.acquire.gpu.global.b32 %0, [%1];" : "=r"(v) : "l"(c) : "memory");
        if (v >= 8) return;
        if (++tries > 64) __nanosleep(64);
    }
}
// Release-increment (no full membar needed; preceded by __syncthreads for CTA writes).
__device__ __forceinline__ void signal(int* c) {
    asm volatile("red.release.gpu.global.add.s32 [%0], 1;" :: "l"(c) : "memory");
}

__global__ void __launch_bounds__(256, 1)
scan_kernel(const float* __restrict__ Uz, const float* __restrict__ Ur,
            const float* __restrict__ Uh, const float* __restrict__ bz,
            const float* __restrict__ br, const float* __restrict__ bh) {
    const int tid   = threadIdx.x;
    const int sub   = tid & 7;          // 8 lanes per row
    const int rrel  = tid >> 3;         // 0..31 row within chunk
    const int chunk = blockIdx.x & 7;   // fixed 32-row slice for this CTA
    const int pslot = blockIdx.x >> 3;  // node slot 0..NSLOT-1
    const int r0    = chunk * 32 + rrel;

    // loop-invariant U slices in registers
    float4 uzr[8], urr[8], uhr[8];
    {
        const float* a = Uz + (size_t)r0 * HID + sub * 4;
        const float* b = Ur + (size_t)r0 * HID + sub * 4;
        const float* c = Uh + (size_t)r0 * HID + sub * 4;
        #pragma unroll
        for (int k = 0; k < 8; k++) {
            uzr[k] = *(const float4*)(a + k * 32);
            urr[k] = *(const float4*)(b + k * 32);
            uhr[k] = *(const float4*)(c + k * 32);
        }
    }
    const float bzv = bz[r0], brv = br[r0], bhv = bh[r0];
    const int nlev = d_nlevels;

    for (int L = 1; L < nlev; L++) {
        const int s = d_level_start[L];
        const int e = d_level_start[L + 1];
        const int W = e - s;

        for (int i = pslot; i < W; i += NSLOT) {
            const int n = d_order[s + i];
            const int p = d_par[n];

            // prefetch pre-GEMM activations while (possibly) waiting
            float yz = 0.f, yr = 0.f, yh = 0.f;
            if (sub == 0) {
                yz = d_Yz[(size_t)n * HID + r0];
                yr = d_Yr[(size_t)n * HID + r0];
                yh = d_Yh[(size_t)n * HID + r0];
            }

            // ---- wait for parent h; load my slice directly from gmem ----
            wait_ge8(&d_cnt_h[p]);
            const float* phb = d_H + (size_t)p * HID;
            float4 ph[8];
            #pragma unroll
            for (int k = 0; k < 8; k++)
                ph[k] = *(const float4*)(phb + sub * 4 + k * 32);
            const float phv = phb[r0];   // parent h at my output row

            // ---- r matvec first; publish u = ph*r ASAP ----
            float ar = 0.f;
            #pragma unroll
            for (int k = 0; k < 8; k++)
                ar = fmaf(urr[k].x, ph[k].x, fmaf(urr[k].y, ph[k].y,
                     fmaf(urr[k].z, ph[k].z, fmaf(urr[k].w, ph[k].w, ar))));
            #pragma unroll
            for (int o = 1; o < 8; o <<= 1)
                ar += __shfl_xor_sync(0xffffffffu, ar, o);
            if (sub == 0) {
                float rr = sigm(yr + ar + brv);
                d_Ubuf[(size_t)n * HID + r0] = phv * rr;
            }
            __syncthreads();                 // all 32 u-rows of this chunk written
            if (tid == 0) signal(&d_cnt_u[n]);

            // ---- z matvec (overlaps other CTAs publishing their u chunks) ----
            float az = 0.f;
            #pragma unroll
            for (int k = 0; k < 8; k++)
                az = fmaf(uzr[k].x, ph[k].x, fmaf(uzr[k].y, ph[k].y,
                     fmaf(uzr[k].z, ph[k].z, fmaf(uzr[k].w, ph[k].w, az))));
            #pragma unroll
            for (int o = 1; o < 8; o <<= 1)
                az += __shfl_xor_sync(0xffffffffu, az, o);
            const float zv = sigm(yz + az + bzv);   // valid on sub==0 lanes

            // ---- wait for full u; load my slice; h matvec ----
            wait_ge8(&d_cnt_u[n]);
            const float* ub = d_Ubuf + (size_t)n * HID;
            float4 uv[8];
            #pragma unroll
            for (int k = 0; k < 8; k++)
                uv[k] = *(const float4*)(ub + sub * 4 + k * 32);
            float ah = 0.f;
            #pragma unroll
            for (int k = 0; k < 8; k++)
                ah = fmaf(uhr[k].x, uv[k].x, fmaf(uhr[k].y, uv[k].y,
                     fmaf(uhr[k].z, uv[k].z, fmaf(uhr[k].w, uv[k].w, ah))));
            #pragma unroll
            for (int o = 1; o < 8; o <<= 1)
                ah += __shfl_xor_sync(0xffffffffu, ah, o);

            if (sub == 0) {
                float c = tanhf(yh + ah + bhv);
                d_H[(size_t)n * HID + r0] = zv * phv + (1.f - zv) * c;
            }
            __syncthreads();                 // all 32 h-rows written
            if (tid == 0) signal(&d_cnt_h[n]);
        }
    }
}

// ---------------- leaf max (partial) ----------------
__global__ void leafmax(const int* __restrict__ leaf) {
    int b = blockIdx.x, tid = threadIdx.x;
    float m = -1e30f;
    for (int l = b * 128; l < (b + 1) * 128; l++) {
        int idx = leaf[l];
        m = fmaxf(m, d_H[(size_t)idx * HID + tid]);
    }
    d_Pmax[b * HID + tid] = m;
}

// ---------------- combine + W_out matvec + softmax + loss ----------------
__global__ void finalk(const float* __restrict__ y, const float* __restrict__ Wout,
                       const float* __restrict__ bout, float* __restrict__ out,
                       int out_size) {
    __shared__ float fs[HID];
    __shared__ float logits[NCLASS];
    int tid = threadIdx.x;
    float m = -1e30f;
    #pragma unroll
    for (int b = 0; b < 16; b++) m = fmaxf(m, d_Pmax[b * HID + tid]);
    fs[tid] = m;
    __syncthreads();
    if (tid < NCLASS) {
        float acc = 0.f;
        for (int h = 0; h < HID; h++) acc = fmaf(Wout[tid * HID + h], fs[h], acc);
        logits[tid] = acc + bout[tid];
    }
    __syncthreads();
    if (tid == 0) {
        float mx = logits[0];
        for (int c = 1; c < NCLASS; c++) mx = fmaxf(mx, logits[c]);
        float ex[NCLASS], ssum = 0.f;
        for (int c = 0; c < NCLASS; c++) { ex[c] = __expf(logits[c] - mx); ssum += ex[c]; }
        float loss = 0.f;
        for (int c = 0; c < NCLASS; c++) {
            float p = ex[c] / ssum;
            if (c < out_size) out[c] = p;
            float d = y[c] - p;
            loss += d * d;
        }
        if (out_size > NCLASS) out[NCLASS] = loss;
    }
}

// ---------------- launcher ----------------
extern "C" void kernel_launch(void* const* d_in, const int* in_sizes, int n_in,
                              void* d_out, int out_size) {
    const int*   tree = (const int*)d_in[0];
    const int*   edge = (const int*)d_in[1];
    const int*   leaf = (const int*)d_in[2];
    const float* y    = (const float*)d_in[3];
    const float* E    = (const float*)d_in[4];
    const float* Wz   = (const float*)d_in[5];
    const float* Uz   = (const float*)d_in[6];
    const float* bz   = (const float*)d_in[7];
    const float* Wr   = (const float*)d_in[8];
    const float* Ur   = (const float*)d_in[9];
    const float* br   = (const float*)d_in[10];
    const float* Wh   = (const float*)d_in[11];
    const float* Uh   = (const float*)d_in[12];
    const float* bh   = (const float*)d_in[13];
    const float* Wout = (const float*)d_in[14];
    const float* bout = (const float*)d_in[15];
    float* out = (float*)d_out;

    transposeE<<<dim3((VOCAB + 31) / 32, HID / 32), dim3(32, 8)>>>(E);
    gatherX<<<NN, HID>>>(tree);
    gemm3<<<dim3(NN / 128, HID / 64, 3), 256>>>(Wz, Wr, Wh);
    prep<<<1, 1024>>>(edge);
    scan_kernel<<<GSCAN, 256>>>(Uz, Ur, Uh, bz, br, bh);
    leafmax<<<16, HID>>>(leaf);
    finalk<<<1, HID>>>(y, Wout, bout, out, out_size);
}

// round 16
// speedup vs baseline: 2.0997x; 1.0913x over previous
#include <cuda_runtime.h>
#include <cuda_bf16.h>
#include <cstdint>

#define NN     4096
#define WORDS  64
#define HID    256
#define VOCAB  50257
#define NCLASS 4
#define NLEAF  2048

#define NSLOT  18            // node slots
#define GSCAN  (NSLOT * 8)   // 144 persistent CTAs: 8 row-chunks x 18 node slots
#define BATCH  8             // nodes per slot batched between phase1/phase2

// ---------------- scratch (device globals; no mallocs allowed) ----------------
__device__ float d_ET[(size_t)VOCAB * HID];   // E transposed: [VOCAB][HID]
__device__ float d_X [(size_t)NN * HID];
__device__ float d_Yz[(size_t)NN * HID];
__device__ float d_Yr[(size_t)NN * HID];
__device__ float d_Yh[(size_t)NN * HID];
__device__ float d_H [(size_t)NN * HID];
__device__ float d_Ubuf[(size_t)NN * HID];
__device__ int   d_par[NN];
__device__ int   d_order[NN];
__device__ int   d_level_start[NN + 1];
__device__ int   d_offs[NN];
__device__ int   d_nlevels;
__device__ int   d_cnt_u[NN];   // per-node: # chunk-CTAs done with phase 1 (u rows)
__device__ int   d_cnt_h[NN];   // per-node: # chunk-CTAs done with phase 2 (h rows)
__device__ float d_Pmax[16 * HID];

// ---------------- E transpose: E(HID,VOCAB) -> ET(VOCAB,HID) ----------------
__global__ void transposeE(const float* __restrict__ E) {
    __shared__ float tile[32][33];
    int v0 = blockIdx.x * 32, h0 = blockIdx.y * 32;
    int x = threadIdx.x, y = threadIdx.y;   // 32 x 8
    #pragma unroll
    for (int i = 0; i < 32; i += 8) {
        int h = h0 + y + i, v = v0 + x;
        tile[y + i][x] = (v < VOCAB) ? E[(size_t)h * VOCAB + v] : 0.f;
    }
    __syncthreads();
    #pragma unroll
    for (int i = 0; i < 32; i += 8) {
        int v = v0 + y + i;
        if (v < VOCAB) d_ET[(size_t)v * HID + h0 + x] = tile[x][y + i];
    }
}

// ---------------- X[n,h] = sum_w ET[tree[n,w], h];  also H[0] = X[0] ----------------
__global__ void gatherX(const int* __restrict__ tree) {
    __shared__ int wv[WORDS];
    int n = blockIdx.x;
    if (threadIdx.x < WORDS) wv[threadIdx.x] = tree[n * WORDS + threadIdx.x];
    __syncthreads();
    int h = threadIdx.x;
    float acc = 0.f;
    #pragma unroll 8
    for (int w = 0; w < WORDS; w++) acc += d_ET[(size_t)wv[w] * HID + h];
    d_X[(size_t)n * HID + h] = acc;
    if (n == 0) d_H[h] = acc;   // node_h0[0] = X[0]
}

// ---------------- Y{z,r,h} = X @ W{z,r,h}^T  (4096x256 @ 256x256) ----------------
__global__ void gemm3(const float* __restrict__ Wz, const float* __restrict__ Wr,
                      const float* __restrict__ Wh) {
    const float* W = (blockIdx.z == 0) ? Wz : (blockIdx.z == 1) ? Wr : Wh;
    float* Y       = (blockIdx.z == 0) ? d_Yz : (blockIdx.z == 1) ? d_Yr : d_Yh;
    __shared__ float As[128][17];
    __shared__ float Bs[64][17];
    const int tid = threadIdx.x;
    const int tx = tid & 15, ty = tid >> 4;
    const int bm = blockIdx.x, bn = blockIdx.y;
    float acc[8][4];
    #pragma unroll
    for (int i = 0; i < 8; i++)
        #pragma unroll
        for (int j = 0; j < 4; j++) acc[i][j] = 0.f;

    const int arow = tid >> 1, ac8 = (tid & 1) * 8;
    const int brow = tid >> 2, bc4 = (tid & 3) * 4;

    for (int k0 = 0; k0 < HID; k0 += 16) {
        float4 va = *(const float4*)(d_X + (size_t)(bm * 128 + arow) * HID + k0 + ac8);
        float4 vb = *(const float4*)(d_X + (size_t)(bm * 128 + arow) * HID + k0 + ac8 + 4);
        As[arow][ac8 + 0] = va.x; As[arow][ac8 + 1] = va.y;
        As[arow][ac8 + 2] = va.z; As[arow][ac8 + 3] = va.w;
        As[arow][ac8 + 4] = vb.x; As[arow][ac8 + 5] = vb.y;
        As[arow][ac8 + 6] = vb.z; As[arow][ac8 + 7] = vb.w;
        float4 wb = *(const float4*)(W + (size_t)(bn * 64 + brow) * HID + k0 + bc4);
        Bs[brow][bc4 + 0] = wb.x; Bs[brow][bc4 + 1] = wb.y;
        Bs[brow][bc4 + 2] = wb.z; Bs[brow][bc4 + 3] = wb.w;
        __syncthreads();
        #pragma unroll
        for (int kk = 0; kk < 16; kk++) {
            float a[8], b[4];
            #pragma unroll
            for (int i = 0; i < 8; i++) a[i] = As[ty * 8 + i][kk];
            #pragma unroll
            for (int j = 0; j < 4; j++) b[j] = Bs[tx * 4 + j][kk];
            #pragma unroll
            for (int i = 0; i < 8; i++)
                #pragma unroll
                for (int j = 0; j < 4; j++) acc[i][j] = fmaf(a[i], b[j], acc[i][j]);
        }
        __syncthreads();
    }
    #pragma unroll
    for (int i = 0; i < 8; i++) {
        int m = bm * 128 + ty * 8 + i;
        float4 o = make_float4(acc[i][0], acc[i][1], acc[i][2], acc[i][3]);
        *(float4*)(Y + (size_t)m * HID + bn * 64 + tx * 4) = o;
    }
}

// ---------------- prep: levels (pointer doubling) + counting sort + counter reset ----------------
__global__ void prep(const int* __restrict__ edge) {
    __shared__ int s_jump[NN];
    __shared__ int s_add[NN];
    __shared__ int s_scan[1024];
    __shared__ int s_maxl;
    const int tid = threadIdx.x;
    if (tid == 0) s_maxl = 0;
    for (int i = tid; i < NN; i += 1024) {
        int p = edge[2 * i];
        d_par[i]  = p;
        s_jump[i] = (i == 0) ? 0 : p;
        s_add[i]  = (i == 0) ? 0 : 1;
        d_cnt_u[i] = 0;
        d_cnt_h[i] = (i == 0) ? 8 : 0;   // node 0's h comes from gatherX
    }
    __syncthreads();
    for (int r = 0; r < 12; r++) {
        int nj[4], na[4];
        #pragma unroll
        for (int k = 0; k < 4; k++) {
            int i = tid + k * 1024;
            int j = s_jump[i];
            nj[k] = s_jump[j];
            na[k] = s_add[i] + s_add[j];
        }
        __syncthreads();
        #pragma unroll
        for (int k = 0; k < 4; k++) {
            int i = tid + k * 1024;
            s_jump[i] = nj[k];
            s_add[i]  = na[k];
        }
        __syncthreads();
    }
    // s_add[i] == level(i). Histogram into s_jump (reused).
    for (int i = tid; i < NN; i += 1024) s_jump[i] = 0;
    __syncthreads();
    #pragma unroll
    for (int k = 0; k < 4; k++) {
        int i = tid + k * 1024;
        atomicMax(&s_maxl, s_add[i]);
        atomicAdd(&s_jump[s_add[i]], 1);
    }
    __syncthreads();
    int c0 = s_jump[4 * tid], c1 = s_jump[4 * tid + 1];
    int c2 = s_jump[4 * tid + 2], c3 = s_jump[4 * tid + 3];
    int part = c0 + c1 + c2 + c3;
    s_scan[tid] = part;
    __syncthreads();
    for (int off = 1; off < 1024; off <<= 1) {
        int v = (tid >= off) ? s_scan[tid - off] : 0;
        __syncthreads();
        s_scan[tid] += v;
        __syncthreads();
    }
    int basep = s_scan[tid] - part;
    d_level_start[4 * tid]     = basep;
    d_level_start[4 * tid + 1] = basep + c0;
    d_level_start[4 * tid + 2] = basep + c0 + c1;
    d_level_start[4 * tid + 3] = basep + c0 + c1 + c2;
    d_offs[4 * tid]     = basep;
    d_offs[4 * tid + 1] = basep + c0;
    d_offs[4 * tid + 2] = basep + c0 + c1;
    d_offs[4 * tid + 3] = basep + c0 + c1 + c2;
    if (tid == 0) d_level_start[NN] = NN;
    __syncthreads();
    #pragma unroll
    for (int k = 0; k < 4; k++) {
        int i = tid + k * 1024;
        int lvl = s_add[i];
        int pos = atomicAdd(&d_offs[lvl], 1);
        d_order[pos] = i;
    }
    if (tid == 0) d_nlevels = s_maxl + 1;
}

// ---------------- persistent dataflow GRU scan (batched phases) ----------------
__device__ __forceinline__ float sigm(float x) { return 1.f / (1.f + __expf(-x)); }

// All threads poll with acquire loads; fast path sleep-free, backoff after 64 tries.
__device__ __forceinline__ void wait_ge8(int* c) {
    int v, tries = 0;
    for (;;) {
        asm volatile("ld.acquire.gpu.global.b32 %0, [%1];" : "=r"(v) : "l"(c) : "memory");
        if (v >= 8) return;
        if (++tries > 64) __nanosleep(64);
    }
}
// Release-increment (no full membar needed; preceded by __syncthreads for CTA writes).
__device__ __forceinline__ void signal(int* c) {
    asm volatile("red.release.gpu.global.add.s32 [%0], 1;" :: "l"(c) : "memory");
}

__global__ void __launch_bounds__(256, 1)
scan_kernel(const float* __restrict__ Uz, const float* __restrict__ Ur,
            const float* __restrict__ Uh, const float* __restrict__ bz,
            const float* __restrict__ br, const float* __restrict__ bh) {
    __shared__ float s_z[BATCH][32];   // z  per (batch node, row) — same-thread reuse
    __shared__ float s_p[BATCH][32];   // ph per (batch node, row)
    const int tid   = threadIdx.x;
    const int sub   = tid & 7;          // 8 lanes per row
    const int rrel  = tid >> 3;         // 0..31 row within chunk
    const int chunk = blockIdx.x & 7;   // fixed 32-row slice for this CTA
    const int pslot = blockIdx.x >> 3;  // node slot 0..NSLOT-1
    const int r0    = chunk * 32 + rrel;

    // loop-invariant U slices in registers
    float4 uzr[8], urr[8], uhr[8];
    {
        const float* a = Uz + (size_t)r0 * HID + sub * 4;
        const float* b = Ur + (size_t)r0 * HID + sub * 4;
        const float* c = Uh + (size_t)r0 * HID + sub * 4;
        #pragma unroll
        for (int k = 0; k < 8; k++) {
            uzr[k] = *(const float4*)(a + k * 32);
            urr[k] = *(const float4*)(b + k * 32);
            uhr[k] = *(const float4*)(c + k * 32);
        }
    }
    const float bzv = bz[r0], brv = br[r0], bhv = bh[r0];
    const int nlev = d_nlevels;

    for (int L = 1; L < nlev; L++) {
        const int s = d_level_start[L];
        const int e = d_level_start[L + 1];
        const int W = e - s;

        for (int i0 = pslot; i0 < W; i0 += NSLOT * BATCH) {
            const int nb = min(BATCH, (W - i0 + NSLOT - 1) / NSLOT);

            // ================= phase 1: r -> publish u -> z (per node) =================
            for (int j = 0; j < nb; j++) {
                const int n = d_order[s + i0 + j * NSLOT];
                const int p = d_par[n];

                float yz = 0.f, yr = 0.f;
                if (sub == 0) {
                    yz = d_Yz[(size_t)n * HID + r0];
                    yr = d_Yr[(size_t)n * HID + r0];
                }

                wait_ge8(&d_cnt_h[p]);
                const float* phb = d_H + (size_t)p * HID;
                float4 ph[8];
                #pragma unroll
                for (int k = 0; k < 8; k++)
                    ph[k] = *(const float4*)(phb + sub * 4 + k * 32);
                const float phv = phb[r0];

                // r matvec; publish u = ph*r ASAP
                float ar = 0.f;
                #pragma unroll
                for (int k = 0; k < 8; k++)
                    ar = fmaf(urr[k].x, ph[k].x, fmaf(urr[k].y, ph[k].y,
                         fmaf(urr[k].z, ph[k].z, fmaf(urr[k].w, ph[k].w, ar))));
                #pragma unroll
                for (int o = 1; o < 8; o <<= 1)
                    ar += __shfl_xor_sync(0xffffffffu, ar, o);
                if (sub == 0) {
                    float rr = sigm(yr + ar + brv);
                    d_Ubuf[(size_t)n * HID + r0] = phv * rr;
                }
                __syncthreads();                 // all 32 u-rows of this chunk written
                if (tid == 0) signal(&d_cnt_u[n]);

                // z matvec (overlaps u-hops)
                float az = 0.f;
                #pragma unroll
                for (int k = 0; k < 8; k++)
                    az = fmaf(uzr[k].x, ph[k].x, fmaf(uzr[k].y, ph[k].y,
                         fmaf(uzr[k].z, ph[k].z, fmaf(uzr[k].w, ph[k].w, az))));
                #pragma unroll
                for (int o = 1; o < 8; o <<= 1)
                    az += __shfl_xor_sync(0xffffffffu, az, o);
                if (sub == 0) {
                    s_z[j][rrel] = sigm(yz + az + bzv);
                    s_p[j][rrel] = phv;
                }
            }

            // ================= phase 2: wait u -> h -> publish (per node) =================
            for (int j = 0; j < nb; j++) {
                const int n = d_order[s + i0 + j * NSLOT];
                float yh = 0.f;
                if (sub == 0) yh = d_Yh[(size_t)n * HID + r0];

                wait_ge8(&d_cnt_u[n]);
                const float* ub = d_Ubuf + (size_t)n * HID;
                float4 uv[8];
                #pragma unroll
                for (int k = 0; k < 8; k++)
                    uv[k] = *(const float4*)(ub + sub * 4 + k * 32);
                float ah = 0.f;
                #pragma unroll
                for (int k = 0; k < 8; k++)
                    ah = fmaf(uhr[k].x, uv[k].x, fmaf(uhr[k].y, uv[k].y,
                         fmaf(uhr[k].z, uv[k].z, fmaf(uhr[k].w, uv[k].w, ah))));
                #pragma unroll
                for (int o = 1; o < 8; o <<= 1)
                    ah += __shfl_xor_sync(0xffffffffu, ah, o);

                if (sub == 0) {
                    float c  = tanhf(yh + ah + bhv);
                    float zv = s_z[j][rrel];
                    float pv = s_p[j][rrel];
                    d_H[(size_t)n * HID + r0] = zv * pv + (1.f - zv) * c;
                }
                __syncthreads();                 // all 32 h-rows written
                if (tid == 0) signal(&d_cnt_h[n]);
            }
        }
    }
}

// ---------------- leaf max (partial) ----------------
__global__ void leafmax(const int* __restrict__ leaf) {
    int b = blockIdx.x, tid = threadIdx.x;
    float m = -1e30f;
    for (int l = b * 128; l < (b + 1) * 128; l++) {
        int idx = leaf[l];
        m = fmaxf(m, d_H[(size_t)idx * HID + tid]);
    }
    d_Pmax[b * HID + tid] = m;
}

// ---------------- combine + W_out matvec + softmax + loss ----------------
__global__ void finalk(const float* __restrict__ y, const float* __restrict__ Wout,
                       const float* __restrict__ bout, float* __restrict__ out,
                       int out_size) {
    __shared__ float fs[HID];
    __shared__ float logits[NCLASS];
    int tid = threadIdx.x;
    float m = -1e30f;
    #pragma unroll
    for (int b = 0; b < 16; b++) m = fmaxf(m, d_Pmax[b * HID + tid]);
    fs[tid] = m;
    __syncthreads();
    if (tid < NCLASS) {
        float acc = 0.f;
        for (int h = 0; h < HID; h++) acc = fmaf(Wout[tid * HID + h], fs[h], acc);
        logits[tid] = acc + bout[tid];
    }
    __syncthreads();
    if (tid == 0) {
        float mx = logits[0];
        for (int c = 1; c < NCLASS; c++) mx = fmaxf(mx, logits[c]);
        float ex[NCLASS], ssum = 0.f;
        for (int c = 0; c < NCLASS; c++) { ex[c] = __expf(logits[c] - mx); ssum += ex[c]; }
        float loss = 0.f;
        for (int c = 0; c < NCLASS; c++) {
            float p = ex[c] / ssum;
            if (c < out_size) out[c] = p;
            float d = y[c] - p;
            loss += d * d;
        }
        if (out_size > NCLASS) out[NCLASS] = loss;
    }
}

// ---------------- launcher ----------------
extern "C" void kernel_launch(void* const* d_in, const int* in_sizes, int n_in,
                              void* d_out, int out_size) {
    const int*   tree = (const int*)d_in[0];
    const int*   edge = (const int*)d_in[1];
    const int*   leaf = (const int*)d_in[2];
    const float* y    = (const float*)d_in[3];
    const float* E    = (const float*)d_in[4];
    const float* Wz   = (const float*)d_in[5];
    const float* Uz   = (const float*)d_in[6];
    const float* bz   = (const float*)d_in[7];
    const float* Wr   = (const float*)d_in[8];
    const float* Ur   = (const float*)d_in[9];
    const float* br   = (const float*)d_in[10];
    const float* Wh   = (const float*)d_in[11];
    const float* Uh   = (const float*)d_in[12];
    const float* bh   = (const float*)d_in[13];
    const float* Wout = (const float*)d_in[14];
    const float* bout = (const float*)d_in[15];
    float* out = (float*)d_out;

    transposeE<<<dim3((VOCAB + 31) / 32, HID / 32), dim3(32, 8)>>>(E);
    gatherX<<<NN, HID>>>(tree);
    gemm3<<<dim3(NN / 128, HID / 64, 3), 256>>>(Wz, Wr, Wh);
    prep<<<1, 1024>>>(edge);
    scan_kernel<<<GSCAN, 256>>>(Uz, Ur, Uh, bz, br, bh);
    leafmax<<<16, HID>>>(leaf);
    finalk<<<1, HID>>>(y, Wout, bout, out, out_size);
}